// round 1
// baseline (speedup 1.0000x reference)
#include <cuda_runtime.h>
#include <math.h>

#define NSP   16384
#define NPIX  (512*512)
#define NE    262144

// ---------------------------------------------------------------------------
// Static scratch (no allocations allowed)
// ---------------------------------------------------------------------------
struct __align__(256) Scratch {
    float sp [NSP * 128];     // pooled superpixel features
    float hb0[NSP * 128];     // layer ping
    float hb1[NSP * 128];     // layer pong
    float h4 [NSP * 128];     // H1+H2+H3 accumulator
    float ab [NSP * 256];     // per-node [A | B] for current layer
    float wp1[128 * 256];     // W1 folded: [k][0:128]=Wa-Wb, [128:256]=Wb
    float wp2[128 * 256];     // W2 folded
    float wfold[128 * 144];   // [o][tap][n] folded conv*linear
    float biasf[16];          // bc@Wl + bl
    float P  [NSP * 144];     // [s][tap][n] per-superpixel tap contributions
    int deg_pix[NSP]; int off_pix[NSP + 1]; int cur_pix[NSP];
    int deg_e  [NSP]; int off_e  [NSP + 1]; int cur_e  [NSP];
    int pix_lst[NPIX];        // pixels grouped by seg
    int src_lst[NE];          // edge srcs grouped by dst
};
__device__ Scratch g_s;

// ---------------------------------------------------------------------------
// Small helpers
// ---------------------------------------------------------------------------
__device__ __forceinline__ float4 f4max(float4 a, float4 b) {
    return make_float4(fmaxf(a.x, b.x), fmaxf(a.y, b.y),
                       fmaxf(a.z, b.z), fmaxf(a.w, b.w));
}
__device__ __forceinline__ float4 f4add(float4 a, float4 b) {
    return make_float4(a.x + b.x, a.y + b.y, a.z + b.z, a.w + b.w);
}

// ---------------------------------------------------------------------------
// CSR construction: histogram -> scan -> scatter
// ---------------------------------------------------------------------------
__global__ void k_zero2(int* a, int* b, int n) {
    int i = blockIdx.x * blockDim.x + threadIdx.x;
    if (i < n) { a[i] = 0; b[i] = 0; }
}

__global__ void k_hist(const int* __restrict__ keys, int* __restrict__ deg, int n) {
    int i = blockIdx.x * blockDim.x + threadIdx.x;
    if (i < n) atomicAdd(&deg[keys[i]], 1);
}

// one block per array (blockIdx.x selects pix/edge), 1024 thr, 16 elems/thr
__global__ void k_scan(int* dp, int* op, int* cp, int* de, int* oe, int* ce) {
    int *deg, *off, *cur;
    if (blockIdx.x == 0) { deg = dp; off = op; cur = cp; }
    else                 { deg = de; off = oe; cur = ce; }
    __shared__ int part[1024];
    int tid = threadIdx.x, base = tid * 16;
    int loc[16]; int s = 0;
#pragma unroll
    for (int i = 0; i < 16; i++) { loc[i] = s; s += deg[base + i]; }
    part[tid] = s; __syncthreads();
    for (int d = 1; d < 1024; d <<= 1) {
        int v = (tid >= d) ? part[tid - d] : 0;
        __syncthreads();
        part[tid] += v;
        __syncthreads();
    }
    int excl = tid ? part[tid - 1] : 0;
#pragma unroll
    for (int i = 0; i < 16; i++) { int o = excl + loc[i]; off[base + i] = o; cur[base + i] = o; }
    if (tid == 1023) off[NSP] = part[1023];
}

__global__ void k_scat_pix(const int* __restrict__ seg, int* __restrict__ cur,
                           int* __restrict__ lst) {
    int i = blockIdx.x * blockDim.x + threadIdx.x;
    if (i < NPIX) { int p = atomicAdd(&cur[seg[i]], 1); lst[p] = i; }
}
__global__ void k_scat_e(const int* __restrict__ ei, int* __restrict__ cur,
                         int* __restrict__ lst) {
    int e = blockIdx.x * blockDim.x + threadIdx.x;
    if (e < NE) { int d = ei[NE + e]; int p = atomicAdd(&cur[d], 1); lst[p] = ei[e]; }
}

// ---------------------------------------------------------------------------
// Mean pooling: one warp per superpixel, lanes cover 128 channels via float4
// ---------------------------------------------------------------------------
__global__ void k_pool(const float* __restrict__ x, const int* __restrict__ off,
                       const int* __restrict__ lst, float* __restrict__ sp) {
    int w = (blockIdx.x * blockDim.x + threadIdx.x) >> 5;
    if (w >= NSP) return;
    int lane = threadIdx.x & 31;
    int beg = off[w], end = off[w + 1];
    float4 acc = make_float4(0.f, 0.f, 0.f, 0.f);
    int j = beg;
    for (; j + 4 <= end; j += 4) {
        int p0 = lst[j], p1 = lst[j + 1], p2 = lst[j + 2], p3 = lst[j + 3];
        float4 v0 = ((const float4*)(x + (size_t)p0 * 128))[lane];
        float4 v1 = ((const float4*)(x + (size_t)p1 * 128))[lane];
        float4 v2 = ((const float4*)(x + (size_t)p2 * 128))[lane];
        float4 v3 = ((const float4*)(x + (size_t)p3 * 128))[lane];
        acc = f4add(acc, f4add(f4add(v0, v1), f4add(v2, v3)));
    }
    for (; j < end; j++) {
        int p = lst[j];
        acc = f4add(acc, ((const float4*)(x + (size_t)p * 128))[lane]);
    }
    float inv = 1.0f / fmaxf((float)(end - beg), 1.0f);
    acc.x *= inv; acc.y *= inv; acc.z *= inv; acc.w *= inv;
    ((float4*)(sp + (size_t)w * 128))[lane] = acc;
}

// ---------------------------------------------------------------------------
// Build W' = [Wa - Wb | Wb] from W [256,128] row-major
// ---------------------------------------------------------------------------
__global__ void k_wp(const float* __restrict__ W, float* __restrict__ Wp) {
    int t = blockIdx.x * blockDim.x + threadIdx.x;
    if (t >= 128 * 256) return;
    int j = t & 255, k = t >> 8;
    float v;
    if (j < 128) v = W[k * 128 + j] - W[(k + 128) * 128 + j];
    else         v = W[(k + 128) * 128 + (j - 128)];
    Wp[t] = v;
}

// ---------------------------------------------------------------------------
// fp32 GEMM: C[M,N] = A[M,K] @ B[K,N], row-major. BM=BN=64, BK=16, 256 thr.
// M multiple of 64, K multiple of 16 guaranteed here; N guarded.
// ---------------------------------------------------------------------------
__global__ void k_gemm(const float* __restrict__ A, const float* __restrict__ B,
                       float* __restrict__ Cm, int M, int N, int K) {
    __shared__ float As[16][68];   // [k][m], padded for banks + f4 alignment
    __shared__ float Bs[16][64];   // [k][n]
    int tid = threadIdx.x;
    int tx = tid & 15, ty = tid >> 4;
    int row0 = blockIdx.y * 64, col0 = blockIdx.x * 64;
    float acc[4][4] = {};
    for (int k0 = 0; k0 < K; k0 += 16) {
#pragma unroll
        for (int i = tid; i < 64 * 16; i += 256) {
            int r = i >> 4, c = i & 15;
            As[c][r] = A[(size_t)(row0 + r) * K + k0 + c];
        }
#pragma unroll
        for (int i = tid; i < 16 * 64; i += 256) {
            int r = i >> 6, c = i & 63;
            int gc = col0 + c;
            Bs[r][c] = (gc < N) ? B[(size_t)(k0 + r) * N + gc] : 0.f;
        }
        __syncthreads();
#pragma unroll
        for (int kk = 0; kk < 16; kk++) {
            float4 a4 = *(const float4*)&As[kk][ty * 4];
            float4 b4 = *(const float4*)&Bs[kk][tx * 4];
            float av[4] = { a4.x, a4.y, a4.z, a4.w };
            float bv[4] = { b4.x, b4.y, b4.z, b4.w };
#pragma unroll
            for (int i = 0; i < 4; i++)
#pragma unroll
                for (int j = 0; j < 4; j++) acc[i][j] += av[i] * bv[j];
        }
        __syncthreads();
    }
#pragma unroll
    for (int i = 0; i < 4; i++) {
        int gr = row0 + ty * 4 + i;
        int gc = col0 + tx * 4;
        if (gc < N) {
            float4 v = make_float4(acc[i][0], acc[i][1], acc[i][2], acc[i][3]);
            *(float4*)&Cm[(size_t)gr * N + gc] = v;
        }
    }
}

// ---------------------------------------------------------------------------
// Segmented max over B rows + relu epilogue. One warp per dst node.
// hout = relu(A[dst] + bias + max_src B[src]); h4 (+)= hout
// ---------------------------------------------------------------------------
__global__ void k_segmax(const float* __restrict__ AB, const float* __restrict__ bias,
                         const int* __restrict__ off, const int* __restrict__ lst,
                         float* __restrict__ hout, float* __restrict__ h4, int accum) {
    int w = (blockIdx.x * blockDim.x + threadIdx.x) >> 5;
    if (w >= NSP) return;
    int lane = threadIdx.x & 31;
    int beg = off[w], end = off[w + 1];
    float4 mv = make_float4(-INFINITY, -INFINITY, -INFINITY, -INFINITY);
    int j = beg;
    for (; j + 4 <= end; j += 4) {
        int s0 = lst[j], s1 = lst[j + 1], s2 = lst[j + 2], s3 = lst[j + 3];
        float4 v0 = ((const float4*)(AB + (size_t)s0 * 256 + 128))[lane];
        float4 v1 = ((const float4*)(AB + (size_t)s1 * 256 + 128))[lane];
        float4 v2 = ((const float4*)(AB + (size_t)s2 * 256 + 128))[lane];
        float4 v3 = ((const float4*)(AB + (size_t)s3 * 256 + 128))[lane];
        mv = f4max(mv, f4max(f4max(v0, v1), f4max(v2, v3)));
    }
    for (; j < end; j++) {
        int s0 = lst[j];
        mv = f4max(mv, ((const float4*)(AB + (size_t)s0 * 256 + 128))[lane]);
    }
    float4 a  = ((const float4*)(AB + (size_t)w * 256))[lane];
    float4 bb = ((const float4*)bias)[lane];
    float4 o = make_float4(fmaxf(0.f, a.x + bb.x + mv.x),
                           fmaxf(0.f, a.y + bb.y + mv.y),
                           fmaxf(0.f, a.z + bb.z + mv.z),
                           fmaxf(0.f, a.w + bb.w + mv.w));
    ((float4*)(hout + (size_t)w * 128))[lane] = o;
    float4* hp = (float4*)(h4 + (size_t)w * 128);
    if (accum) { float4 t = hp[lane]; hp[lane] = f4add(t, o); }
    else       hp[lane] = o;
}

// ---------------------------------------------------------------------------
// Fold conv weights through the final linear:
// wfold[o][tap][n] = sum_c Wc[c][o][tap] * Wl[c][n];  biasf = bc@Wl + bl
// ---------------------------------------------------------------------------
__global__ void k_fold(const float* __restrict__ Wc, const float* __restrict__ Wl,
                       const float* __restrict__ bc, const float* __restrict__ bl,
                       float* __restrict__ wfold, float* __restrict__ biasf) {
    int t = blockIdx.x * blockDim.x + threadIdx.x;
    if (t < 128 * 144) {
        int n = t & 15;
        int tap = (t >> 4) % 9;
        int o = t / 144;
        float s = 0.f;
        for (int c = 0; c < 128; c++)
            s += Wc[(size_t)(c * 128 + o) * 9 + tap] * Wl[c * 16 + n];
        wfold[t] = s;
    } else if (t < 128 * 144 + 16) {
        int n = t - 128 * 144;
        float s = bl[n];
        for (int c = 0; c < 128; c++) s += bc[c] * Wl[c * 16 + n];
        biasf[n] = s;
    }
}

// ---------------------------------------------------------------------------
// Final fused unpool+conv+linear: 4 threads per pixel, 4 channels each.
// out[p][n] = biasf[n] + sum_{tap in-bounds} P[seg[nbr]][tap][n]
// ---------------------------------------------------------------------------
__global__ void k_out(const int* __restrict__ seg, const float* __restrict__ P,
                      const float* __restrict__ biasf, float* __restrict__ out) {
    int g = blockIdx.x * blockDim.x + threadIdx.x;
    if (g >= NPIX * 4) return;
    int p = g >> 2, q = g & 3;
    int y = p >> 9, x = p & 511;
    float4 acc = ((const float4*)biasf)[q];
#pragma unroll
    for (int ky = 0; ky < 3; ky++) {
        int ny = y + ky - 1;
        if ((unsigned)ny >= 512u) continue;
#pragma unroll
        for (int kx = 0; kx < 3; kx++) {
            int nx = x + kx - 1;
            if ((unsigned)nx >= 512u) continue;
            int s = seg[(ny << 9) + nx];
            float4 v = ((const float4*)(P + (size_t)s * 144 + (ky * 3 + kx) * 16))[q];
            acc = f4add(acc, v);
        }
    }
    ((float4*)out)[g] = acc;
}

// ---------------------------------------------------------------------------
// Launch
// ---------------------------------------------------------------------------
extern "C" void kernel_launch(void* const* d_in, const int* in_sizes, int n_in,
                              void* d_out, int out_size) {
    const float* x   = (const float*)d_in[0];
    const int*   ei  = (const int*)  d_in[1];
    const int*   seg = (const int*)  d_in[2];
    // n_sp may or may not be materialized as input #3 (scalar). Detect.
    int wi = (n_in >= 12) ? 4 : 3;
    const float* W1 = (const float*)d_in[wi + 0];
    const float* b1 = (const float*)d_in[wi + 1];
    const float* W2 = (const float*)d_in[wi + 2];
    const float* b2 = (const float*)d_in[wi + 3];
    const float* Wc = (const float*)d_in[wi + 4];
    const float* bc = (const float*)d_in[wi + 5];
    const float* Wl = (const float*)d_in[wi + 6];
    const float* bl = (const float*)d_in[wi + 7];
    float* out = (float*)d_out;
    (void)in_sizes; (void)out_size;

    Scratch* s = nullptr;
    cudaGetSymbolAddress((void**)&s, g_s);

    // --- CSR build (pixels by seg, edges by dst) ---
    k_zero2<<<(NSP + 255) / 256, 256>>>(s->deg_pix, s->deg_e, NSP);
    k_hist<<<(NPIX + 255) / 256, 256>>>(seg, s->deg_pix, NPIX);
    k_hist<<<(NE + 255) / 256, 256>>>(ei + NE, s->deg_e, NE);
    k_scan<<<2, 1024>>>(s->deg_pix, s->off_pix, s->cur_pix,
                        s->deg_e, s->off_e, s->cur_e);
    k_scat_pix<<<(NPIX + 255) / 256, 256>>>(seg, s->cur_pix, s->pix_lst);
    k_scat_e<<<(NE + 255) / 256, 256>>>(ei, s->cur_e, s->src_lst);

    // --- mean pool pixels -> superpixels ---
    k_pool<<<(NSP * 32 + 255) / 256, 256>>>(x, s->off_pix, s->pix_lst, s->sp);

    // --- folded EdgeConv weights ---
    k_wp<<<(128 * 256 + 255) / 256, 256>>>(W1, s->wp1);
    k_wp<<<(128 * 256 + 255) / 256, 256>>>(W2, s->wp2);

    dim3 gAB(4, NSP / 64);
    int segGrid = (NSP * 32 + 255) / 256;
    // Layer 1: H1
    k_gemm<<<gAB, 256>>>(s->sp, s->wp1, s->ab, NSP, 256, 128);
    k_segmax<<<segGrid, 256>>>(s->ab, b1, s->off_e, s->src_lst, s->hb0, s->h4, 0);
    // Layer 2: H2 (W2)
    k_gemm<<<gAB, 256>>>(s->hb0, s->wp2, s->ab, NSP, 256, 128);
    k_segmax<<<segGrid, 256>>>(s->ab, b2, s->off_e, s->src_lst, s->hb1, s->h4, 1);
    // Layer 3: H3 (W2 again)
    k_gemm<<<gAB, 256>>>(s->hb1, s->wp2, s->ab, NSP, 256, 128);
    k_segmax<<<segGrid, 256>>>(s->ab, b2, s->off_e, s->src_lst, s->hb0, s->h4, 1);

    // --- fold conv through final linear, then P = H4 @ Wfold ---
    k_fold<<<(128 * 144 + 16 + 255) / 256, 256>>>(Wc, Wl, bc, bl, s->wfold, s->biasf);
    dim3 gP(3, NSP / 64);
    k_gemm<<<gP, 256>>>(s->h4, s->wfold, s->P, NSP, 144, 128);

    // --- final fused unpool + 3x3 conv + linear ---
    k_out<<<(NPIX * 4 + 255) / 256, 256>>>(seg, s->P, s->biasf, out);
}

// round 2
// speedup vs baseline: 2.0099x; 2.0099x over previous
#include <cuda_runtime.h>
#include <math.h>

#define NSP   16384
#define NPIX  (512*512)
#define NE    262144

// ---------------------------------------------------------------------------
// Static scratch (no allocations allowed)
// ---------------------------------------------------------------------------
struct __align__(256) Scratch {
    float sp [NSP * 128];     // pooled superpixel features
    float hb0[NSP * 128];     // layer ping
    float hb1[NSP * 128];     // layer pong
    float h4 [NSP * 128];     // H1+H2+H3 accumulator
    float ab [NSP * 256];     // per-node [A | B] for current layer
    float wp1[128 * 256];     // W1 folded: [k][0:128]=Wa-Wb, [128:256]=Wb
    float wp2[128 * 256];     // W2 folded
    float wfold[128 * 144];   // [o][tap][n] folded conv*linear
    float biasf[16];          // bc@Wl + bl
    float P  [NSP * 144];     // [s][tap][n] per-superpixel tap contributions
    int deg_pix[NSP]; int off_pix[NSP + 1]; int cur_pix[NSP];
    int deg_e  [NSP]; int off_e  [NSP + 1]; int cur_e  [NSP];
    int bsum[128]; int boff[128];
    int pix_lst[NPIX];        // pixels grouped by seg
    int src_lst[NE];          // edge srcs grouped by dst
};
__device__ Scratch g_s;

// ---------------------------------------------------------------------------
// Small helpers
// ---------------------------------------------------------------------------
__device__ __forceinline__ float4 f4max(float4 a, float4 b) {
    return make_float4(fmaxf(a.x, b.x), fmaxf(a.y, b.y),
                       fmaxf(a.z, b.z), fmaxf(a.w, b.w));
}
__device__ __forceinline__ float4 f4add(float4 a, float4 b) {
    return make_float4(a.x + b.x, a.y + b.y, a.z + b.z, a.w + b.w);
}
__device__ __forceinline__ unsigned f2tf32(float f) {
    unsigned u;
    asm("cvt.rna.tf32.f32 %0, %1;" : "=r"(u) : "f"(f));
    return u;
}

// ---------------------------------------------------------------------------
// CSR construction: histogram -> 3-phase scan -> scatter
// ---------------------------------------------------------------------------
__global__ void k_zero2(int* a, int* b, int n) {
    int i = blockIdx.x * blockDim.x + threadIdx.x;
    if (i < n) { a[i] = 0; b[i] = 0; }
}

__global__ void k_hist_both(const int* __restrict__ seg, int* __restrict__ dpix,
                            const int* __restrict__ ei, int* __restrict__ de) {
    int i = blockIdx.x * blockDim.x + threadIdx.x;
    if (i < NPIX) atomicAdd(&dpix[seg[i]], 1);
    if (i < NE)   atomicAdd(&de[ei[NE + i]], 1);
}

// phase 1: 128 blocks (64 pix + 64 edge) of 256; per-block exclusive scan
__global__ void k_scan1(const int* __restrict__ dp, int* __restrict__ op,
                        const int* __restrict__ de, int* __restrict__ oe,
                        int* __restrict__ bsum) {
    int b = blockIdx.x;
    const int* deg = (b < 64) ? dp : de;
    int* off = (b < 64) ? op : oe;
    int base = (b & 63) * 256;
    int tid = threadIdx.x;
    int v = deg[base + tid];
    int x = v;
#pragma unroll
    for (int d = 1; d < 32; d <<= 1) {
        int y = __shfl_up_sync(~0u, x, d);
        if ((tid & 31) >= d) x += y;
    }
    __shared__ int wsum[8];
    if ((tid & 31) == 31) wsum[tid >> 5] = x;
    __syncthreads();
    if (tid < 8) {
        int s = wsum[tid];
#pragma unroll
        for (int d = 1; d < 8; d <<= 1) {
            int y = __shfl_up_sync(0xffu, s, d);
            if (tid >= d) s += y;
        }
        wsum[tid] = s;
    }
    __syncthreads();
    int wpre = (tid >= 32) ? wsum[(tid >> 5) - 1] : 0;
    int incl = x + wpre;
    off[base + tid] = incl - v;
    if (tid == 255) bsum[b] = incl;
}

// phase 2: scan the 128 block totals (two independent 64-segments)
__global__ void k_scan2(const int* __restrict__ bsum, int* __restrict__ boff,
                        int* op, int* oe) {
    if (threadIdx.x == 0) {
        int s = 0;
        for (int i = 0; i < 64; i++) { boff[i] = s; s += bsum[i]; }
        op[NSP] = s;
        s = 0;
        for (int i = 64; i < 128; i++) { boff[i] = s; s += bsum[i]; }
        oe[NSP] = s;
    }
}

// phase 3: add block offsets, emit cur
__global__ void k_scan3(int* __restrict__ op, int* __restrict__ cp,
                        int* __restrict__ oe, int* __restrict__ ce,
                        const int* __restrict__ boff) {
    int b = blockIdx.x, tid = threadIdx.x;
    int* off = (b < 64) ? op : oe;
    int* cur = (b < 64) ? cp : ce;
    int i = (b & 63) * 256 + tid;
    int v = off[i] + boff[b];
    off[i] = v; cur[i] = v;
}

__global__ void k_scat_both(const int* __restrict__ seg, int* __restrict__ cpix,
                            int* __restrict__ plst, const int* __restrict__ ei,
                            int* __restrict__ ce, int* __restrict__ elst) {
    int i = blockIdx.x * blockDim.x + threadIdx.x;
    if (i < NPIX) { int p = atomicAdd(&cpix[seg[i]], 1); plst[p] = i; }
    if (i < NE)   { int d = ei[NE + i]; int p = atomicAdd(&ce[d], 1); elst[p] = ei[i]; }
}

// ---------------------------------------------------------------------------
// Mean pooling: one warp per superpixel, lanes cover 128 channels via float4
// ---------------------------------------------------------------------------
__global__ void k_pool(const float* __restrict__ x, const int* __restrict__ off,
                       const int* __restrict__ lst, float* __restrict__ sp) {
    int w = (blockIdx.x * blockDim.x + threadIdx.x) >> 5;
    if (w >= NSP) return;
    int lane = threadIdx.x & 31;
    int beg = off[w], end = off[w + 1];
    float4 acc = make_float4(0.f, 0.f, 0.f, 0.f);
    int j = beg;
    for (; j + 4 <= end; j += 4) {
        int p0 = lst[j], p1 = lst[j + 1], p2 = lst[j + 2], p3 = lst[j + 3];
        float4 v0 = ((const float4*)(x + (size_t)p0 * 128))[lane];
        float4 v1 = ((const float4*)(x + (size_t)p1 * 128))[lane];
        float4 v2 = ((const float4*)(x + (size_t)p2 * 128))[lane];
        float4 v3 = ((const float4*)(x + (size_t)p3 * 128))[lane];
        acc = f4add(acc, f4add(f4add(v0, v1), f4add(v2, v3)));
    }
    for (; j < end; j++) {
        int p = lst[j];
        acc = f4add(acc, ((const float4*)(x + (size_t)p * 128))[lane]);
    }
    float inv = 1.0f / fmaxf((float)(end - beg), 1.0f);
    acc.x *= inv; acc.y *= inv; acc.z *= inv; acc.w *= inv;
    ((float4*)(sp + (size_t)w * 128))[lane] = acc;
}

// ---------------------------------------------------------------------------
// Build W' = [Wa - Wb | Wb] for both weight matrices in one launch
// ---------------------------------------------------------------------------
__global__ void k_wp_both(const float* __restrict__ W1, float* __restrict__ Wp1,
                          const float* __restrict__ W2, float* __restrict__ Wp2) {
    int t = blockIdx.x * blockDim.x + threadIdx.x;
    if (t >= 2 * 128 * 256) return;
    const float* W = (t < 128 * 256) ? W1 : W2;
    float* Wp = (t < 128 * 256) ? Wp1 : Wp2;
    int u = t & (128 * 256 - 1);
    int j = u & 255, k = u >> 8;
    float v;
    if (j < 128) v = W[k * 128 + j] - W[(k + 128) * 128 + j];
    else         v = W[(k + 128) * 128 + (j - 128)];
    Wp[u] = v;
}

// ---------------------------------------------------------------------------
// TF32 tensor-core GEMM: C[M,N] = A[M,128] @ B[128,N], row-major.
// BM=128, BN=64, BK=32, 256 threads (8 warps, 4x2 warp grid).
// mma.sync.m16n8k8.tf32, fp32 accumulate. M % 128 == 0; N guarded.
// ---------------------------------------------------------------------------
__global__ void k_gemm_tc(const float* __restrict__ A, const float* __restrict__ B,
                          float* __restrict__ Cm, int M, int N) {
    __shared__ unsigned As[128][36];   // [m][k], pad -> conflict-free frag loads
    __shared__ unsigned Bs[32][72];    // [k][n], pad 72 -> conflict-free
    int tid = threadIdx.x;
    int warp = tid >> 5, lane = tid & 31;
    int g = lane >> 2, t = lane & 3;
    int wm = warp & 3, wn = warp >> 2;
    int row0 = blockIdx.y * 128, col0 = blockIdx.x * 64;
    float c[2][4][4] = {};
    for (int k0 = 0; k0 < 128; k0 += 32) {
        // A tile: 128x32 floats = 1024 float4, 4 per thread
#pragma unroll
        for (int it = 0; it < 4; it++) {
            int idx = tid + it * 256;
            int r = idx >> 3, fc = idx & 7;
            float4 v = *(const float4*)(A + (size_t)(row0 + r) * 128 + k0 + fc * 4);
            As[r][fc * 4 + 0] = f2tf32(v.x);
            As[r][fc * 4 + 1] = f2tf32(v.y);
            As[r][fc * 4 + 2] = f2tf32(v.z);
            As[r][fc * 4 + 3] = f2tf32(v.w);
        }
        // B tile: 32x64 floats = 512 float4, 2 per thread
#pragma unroll
        for (int it = 0; it < 2; it++) {
            int idx = tid + it * 256;
            int r = idx >> 4, fc = idx & 15;
            int gc = col0 + fc * 4;
            float4 v = make_float4(0.f, 0.f, 0.f, 0.f);
            if (gc < N) v = *(const float4*)(B + (size_t)(k0 + r) * N + gc);
            Bs[r][fc * 4 + 0] = f2tf32(v.x);
            Bs[r][fc * 4 + 1] = f2tf32(v.y);
            Bs[r][fc * 4 + 2] = f2tf32(v.z);
            Bs[r][fc * 4 + 3] = f2tf32(v.w);
        }
        __syncthreads();
#pragma unroll
        for (int ks = 0; ks < 4; ks++) {
            int kk = ks * 8;
            unsigned a[2][4], b[4][2];
#pragma unroll
            for (int i = 0; i < 2; i++) {
                int rm = wm * 32 + i * 16;
                a[i][0] = As[rm + g][kk + t];
                a[i][1] = As[rm + g + 8][kk + t];
                a[i][2] = As[rm + g][kk + t + 4];
                a[i][3] = As[rm + g + 8][kk + t + 4];
            }
#pragma unroll
            for (int j = 0; j < 4; j++) {
                int cn = wn * 32 + j * 8 + g;
                b[j][0] = Bs[kk + t][cn];
                b[j][1] = Bs[kk + t + 4][cn];
            }
#pragma unroll
            for (int i = 0; i < 2; i++)
#pragma unroll
                for (int j = 0; j < 4; j++) {
                    asm volatile(
                        "mma.sync.aligned.m16n8k8.row.col.f32.tf32.tf32.f32 "
                        "{%0,%1,%2,%3}, {%4,%5,%6,%7}, {%8,%9}, {%0,%1,%2,%3};"
                        : "+f"(c[i][j][0]), "+f"(c[i][j][1]),
                          "+f"(c[i][j][2]), "+f"(c[i][j][3])
                        : "r"(a[i][0]), "r"(a[i][1]), "r"(a[i][2]), "r"(a[i][3]),
                          "r"(b[j][0]), "r"(b[j][1]));
                }
        }
        __syncthreads();
    }
#pragma unroll
    for (int i = 0; i < 2; i++) {
        int r = row0 + wm * 32 + i * 16 + g;
#pragma unroll
        for (int j = 0; j < 4; j++) {
            int cc = col0 + wn * 32 + j * 8 + 2 * t;
            if (cc < N) {
                *(float2*)(Cm + (size_t)r * N + cc) = make_float2(c[i][j][0], c[i][j][1]);
                *(float2*)(Cm + (size_t)(r + 8) * N + cc) = make_float2(c[i][j][2], c[i][j][3]);
            }
        }
    }
}

// ---------------------------------------------------------------------------
// Segmented max over B rows + relu epilogue. One warp per dst node.
// hout = relu(A[dst] + bias + max_src B[src]); h4 (+)= hout
// ---------------------------------------------------------------------------
__global__ void k_segmax(const float* __restrict__ AB, const float* __restrict__ bias,
                         const int* __restrict__ off, const int* __restrict__ lst,
                         float* __restrict__ hout, float* __restrict__ h4, int accum) {
    int w = (blockIdx.x * blockDim.x + threadIdx.x) >> 5;
    if (w >= NSP) return;
    int lane = threadIdx.x & 31;
    int beg = off[w], end = off[w + 1];
    float4 mv = make_float4(-INFINITY, -INFINITY, -INFINITY, -INFINITY);
    int j = beg;
    for (; j + 4 <= end; j += 4) {
        int s0 = lst[j], s1 = lst[j + 1], s2 = lst[j + 2], s3 = lst[j + 3];
        float4 v0 = ((const float4*)(AB + (size_t)s0 * 256 + 128))[lane];
        float4 v1 = ((const float4*)(AB + (size_t)s1 * 256 + 128))[lane];
        float4 v2 = ((const float4*)(AB + (size_t)s2 * 256 + 128))[lane];
        float4 v3 = ((const float4*)(AB + (size_t)s3 * 256 + 128))[lane];
        mv = f4max(mv, f4max(f4max(v0, v1), f4max(v2, v3)));
    }
    for (; j < end; j++) {
        int s0 = lst[j];
        mv = f4max(mv, ((const float4*)(AB + (size_t)s0 * 256 + 128))[lane]);
    }
    float4 a  = ((const float4*)(AB + (size_t)w * 256))[lane];
    float4 bb = ((const float4*)bias)[lane];
    float4 o = make_float4(fmaxf(0.f, a.x + bb.x + mv.x),
                           fmaxf(0.f, a.y + bb.y + mv.y),
                           fmaxf(0.f, a.z + bb.z + mv.z),
                           fmaxf(0.f, a.w + bb.w + mv.w));
    ((float4*)(hout + (size_t)w * 128))[lane] = o;
    float4* hp = (float4*)(h4 + (size_t)w * 128);
    if (accum) { float4 tt = hp[lane]; hp[lane] = f4add(tt, o); }
    else       hp[lane] = o;
}

// ---------------------------------------------------------------------------
// Fold conv weights through the final linear:
// wfold[o][tap][n] = sum_c Wc[c][o][tap] * Wl[c][n];  biasf = bc@Wl + bl
// ---------------------------------------------------------------------------
__global__ void k_fold(const float* __restrict__ Wc, const float* __restrict__ Wl,
                       const float* __restrict__ bc, const float* __restrict__ bl,
                       float* __restrict__ wfold, float* __restrict__ biasf) {
    int t = blockIdx.x * blockDim.x + threadIdx.x;
    if (t < 128 * 144) {
        int n = t & 15;
        int tap = (t >> 4) % 9;
        int o = t / 144;
        float s = 0.f;
        for (int c = 0; c < 128; c++)
            s += Wc[(size_t)(c * 128 + o) * 9 + tap] * Wl[c * 16 + n];
        wfold[t] = s;
    } else if (t < 128 * 144 + 16) {
        int n = t - 128 * 144;
        float s = bl[n];
        for (int c = 0; c < 128; c++) s += bc[c] * Wl[c * 16 + n];
        biasf[n] = s;
    }
}

// ---------------------------------------------------------------------------
// Final fused unpool+conv+linear: 4 threads per pixel, 4 channels each.
// ---------------------------------------------------------------------------
__global__ void k_out(const int* __restrict__ seg, const float* __restrict__ P,
                      const float* __restrict__ biasf, float* __restrict__ out) {
    int gidx = blockIdx.x * blockDim.x + threadIdx.x;
    if (gidx >= NPIX * 4) return;
    int p = gidx >> 2, q = gidx & 3;
    int y = p >> 9, x = p & 511;
    float4 acc = ((const float4*)biasf)[q];
#pragma unroll
    for (int ky = 0; ky < 3; ky++) {
        int ny = y + ky - 1;
        if ((unsigned)ny >= 512u) continue;
#pragma unroll
        for (int kx = 0; kx < 3; kx++) {
            int nx = x + kx - 1;
            if ((unsigned)nx >= 512u) continue;
            int s = seg[(ny << 9) + nx];
            float4 v = ((const float4*)(P + (size_t)s * 144 + (ky * 3 + kx) * 16))[q];
            acc = f4add(acc, v);
        }
    }
    ((float4*)out)[gidx] = acc;
}

// ---------------------------------------------------------------------------
// Launch
// ---------------------------------------------------------------------------
extern "C" void kernel_launch(void* const* d_in, const int* in_sizes, int n_in,
                              void* d_out, int out_size) {
    const float* x   = (const float*)d_in[0];
    const int*   ei  = (const int*)  d_in[1];
    const int*   seg = (const int*)  d_in[2];
    int wi = (n_in >= 12) ? 4 : 3;
    const float* W1 = (const float*)d_in[wi + 0];
    const float* b1 = (const float*)d_in[wi + 1];
    const float* W2 = (const float*)d_in[wi + 2];
    const float* b2 = (const float*)d_in[wi + 3];
    const float* Wc = (const float*)d_in[wi + 4];
    const float* bc = (const float*)d_in[wi + 5];
    const float* Wl = (const float*)d_in[wi + 6];
    const float* bl = (const float*)d_in[wi + 7];
    float* out = (float*)d_out;
    (void)in_sizes; (void)out_size;

    Scratch* s = nullptr;
    cudaGetSymbolAddress((void**)&s, g_s);

    // --- CSR build ---
    k_zero2<<<(NSP + 255) / 256, 256>>>(s->deg_pix, s->deg_e, NSP);
    k_hist_both<<<(NPIX + 255) / 256, 256>>>(seg, s->deg_pix, ei, s->deg_e);
    k_scan1<<<128, 256>>>(s->deg_pix, s->off_pix, s->deg_e, s->off_e, s->bsum);
    k_scan2<<<1, 32>>>(s->bsum, s->boff, s->off_pix, s->off_e);
    k_scan3<<<128, 256>>>(s->off_pix, s->cur_pix, s->off_e, s->cur_e, s->boff);
    k_scat_both<<<(NPIX + 255) / 256, 256>>>(seg, s->cur_pix, s->pix_lst,
                                             ei, s->cur_e, s->src_lst);

    // --- mean pool pixels -> superpixels ---
    k_pool<<<(NSP * 32 + 255) / 256, 256>>>(x, s->off_pix, s->pix_lst, s->sp);

    // --- folded EdgeConv weights ---
    k_wp_both<<<(2 * 128 * 256 + 255) / 256, 256>>>(W1, s->wp1, W2, s->wp2);

    dim3 gAB(4, NSP / 128);
    int segGrid = (NSP * 32 + 255) / 256;
    // Layer 1: H1
    k_gemm_tc<<<gAB, 256>>>(s->sp, s->wp1, s->ab, NSP, 256);
    k_segmax<<<segGrid, 256>>>(s->ab, b1, s->off_e, s->src_lst, s->hb0, s->h4, 0);
    // Layer 2: H2 (W2)
    k_gemm_tc<<<gAB, 256>>>(s->hb0, s->wp2, s->ab, NSP, 256);
    k_segmax<<<segGrid, 256>>>(s->ab, b2, s->off_e, s->src_lst, s->hb1, s->h4, 1);
    // Layer 3: H3 (W2 again)
    k_gemm_tc<<<gAB, 256>>>(s->hb1, s->wp2, s->ab, NSP, 256);
    k_segmax<<<segGrid, 256>>>(s->ab, b2, s->off_e, s->src_lst, s->hb0, s->h4, 1);

    // --- fold conv through final linear, then P = H4 @ Wfold ---
    k_fold<<<(128 * 144 + 16 + 255) / 256, 256>>>(Wc, Wl, bc, bl, s->wfold, s->biasf);
    dim3 gP(3, NSP / 128);
    k_gemm_tc<<<gP, 256>>>(s->h4, s->wfold, s->P, NSP, 144);

    // --- final fused unpool + 3x3 conv + linear ---
    k_out<<<(NPIX * 4 + 255) / 256, 256>>>(seg, s->P, s->biasf, out);
}